// round 17
// baseline (speedup 1.0000x reference)
#include <cuda_runtime.h>
#include <math.h>

// Problem constants
#define M_TOT 32768            // 512*64 matrices
#define BLOCKS 1024
#define THREADS 128
#define WPB 4
#define NWARPS (BLOCKS * WPB)  // 4096 warps -> 8 matrices each (4 pair-iterations)
#define TS 36                  // tile row stride in floats (16B-aligned, conflict-free)
#define TS4 9                  // tile row stride in float4
#define PSTRIDE 33             // stats entry stride
#define PART_ENTRIES (32 * PSTRIDE)   // 1056

// Scratch (static device arrays; no runtime allocation allowed)
__device__ float g_L[(size_t)M_TOT * 1024];        // Cholesky factors, COLUMN-major per matrix
__device__ float g_part[PART_ENTRIES * BLOCKS];    // per-block partials, [entry][block]
__device__ float g_sums[PART_ENTRIES];
__device__ float g_stats[1025];                    // mean[32*32] (diag slot = logd mean) + factor

// ---------------------------------------------------------------------------
// Pass 1: TWO-WAY INTERLEAVED warp-per-matrix Cholesky. Each warp factors two
// matrices through one k-loop: one syncwarp covers both column broadcasts and
// the two dependency chains hide each other's smem latency. Direct symmetric
// X load (row == column), deferred normalization, coalesced column-major L
// store, Log-Cholesky statistics for both matrices.
// ---------------------------------------------------------------------------
__global__ void __launch_bounds__(THREADS) chol_pass1(const float* __restrict__ X) {
    __shared__ float scol[WPB * 128];           // per warp: 2 matrices x 2 buffers x 32
    __shared__ float sred[WPB * PART_ENTRIES];  // block reduction buffer (16.9 KB)
    const int lane = threadIdx.x & 31;
    const int wl   = threadIdx.x >> 5;
    float* colf = scol + wl * 128;
    const int gw = blockIdx.x * WPB + wl;

    float acc[32];
#pragma unroll
    for (int j = 0; j < 32; j++) acc[j] = 0.f;
    float accsq = 0.f;

    for (int m0 = gw; m0 < M_TOT; m0 += 2 * NWARPS) {
        const int m1 = m0 + NWARPS;             // always < M_TOT (8 matrices/warp, even)
        // direct symmetric loads: a[j] = X[m][j][lane] == X[m][lane][j]
        const float* xs0 = X + (size_t)m0 * 1024;
        const float* xs1 = X + (size_t)m1 * 1024;
        float a[32], c[32];
#pragma unroll
        for (int j = 0; j < 32; j++) a[j] = xs0[j * 32 + lane];
#pragma unroll
        for (int j = 0; j < 32; j++) c[j] = xs1[j * 32 + lane];

        float* gl0 = g_L + (size_t)m0 * 1024;
        float* gl1 = g_L + (size_t)m1 * 1024;
        float mydiag0 = 1.f, mydiag1 = 1.f;
#pragma unroll
        for (int k = 0; k < 32; k++) {
            float araw0 = a[k];
            float araw1 = c[k];
            float* cb0 = colf +      ((k & 1) << 5);   // double-buffered broadcasts
            float* cb1 = colf + 64 + ((k & 1) << 5);
            cb0[lane] = araw0;
            cb1[lane] = araw1;
            __syncwarp();
            float akk0 = cb0[k];
            float akk1 = cb1[k];
            float t0 = __fdividef(araw0, akk0);
            float t1 = __fdividef(araw1, akk1);
            float lik0 = araw0 * rsqrtf(akk0);  // lane==k -> sqrt(akk)
            float lik1 = araw1 * rsqrtf(akk1);
            if (lane < k) { lik0 = 0.f; lik1 = 0.f; }
            if (lane == k) { mydiag0 = lik0; mydiag1 = lik1; }
            a[k] = lik0;
            c[k] = lik1;
            gl0[k * 32 + lane] = lik0;          // coalesced column-major stores
            gl1[k * 32 + lane] = lik1;
            // rank-1 updates: a[j] -= t * raw_j (== l_ik * l_jk); the two
            // independent chains interleave and hide the LDS latency.
#pragma unroll
            for (int q = (k + 1) / 4; q < 8; q++) {
                float4 c0 = ((const float4*)cb0)[q];
                float4 c1 = ((const float4*)cb1)[q];
                if (4*q+0 > k) { a[4*q+0] -= t0 * c0.x; c[4*q+0] -= t1 * c1.x; }
                if (4*q+1 > k) { a[4*q+1] -= t0 * c0.y; c[4*q+1] -= t1 * c1.y; }
                if (4*q+2 > k) { a[4*q+2] -= t0 * c0.z; c[4*q+2] -= t1 * c1.z; }
                if (4*q+3 > k) { a[4*q+3] -= t0 * c0.w; c[4*q+3] -= t1 * c1.w; }
            }
        }
        float logd0 = __logf(mydiag0);
        float logd1 = __logf(mydiag1);

        // accumulate Log-Cholesky coords for both matrices
#pragma unroll
        for (int j = 0; j < 32; j++) {
            float v0 = (j < lane) ? a[j] : ((j == lane) ? logd0 : 0.f);
            float v1 = (j < lane) ? c[j] : ((j == lane) ? logd1 : 0.f);
            acc[j] += v0 + v1;
            accsq  += v0 * v0 + v1 * v1;
        }
    }

    // block reduction
    __syncthreads();
#pragma unroll
    for (int j = 0; j < 32; j++)
        sred[wl * PART_ENTRIES + lane * PSTRIDE + j] = acc[j];
    sred[wl * PART_ENTRIES + lane * PSTRIDE + 32] = accsq;
    __syncthreads();

    for (int e = threadIdx.x; e < PART_ENTRIES; e += THREADS) {
        float s = 0.f;
#pragma unroll
        for (int w = 0; w < WPB; w++) s += sred[w * PART_ENTRIES + e];
        g_part[e * BLOCKS + blockIdx.x] = s;   // [entry][block] -> coalesced reduce
    }
}

// ---------------------------------------------------------------------------
// k2a: deterministic tree reduction of 1024 block partials per entry (coalesced).
// ---------------------------------------------------------------------------
__global__ void reduce2a() {
    __shared__ float red[BLOCKS];
    const int e = blockIdx.x;
    red[threadIdx.x] = g_part[e * BLOCKS + threadIdx.x];
    __syncthreads();
#pragma unroll
    for (int s = BLOCKS / 2; s > 0; s >>= 1) {
        if ((int)threadIdx.x < s) red[threadIdx.x] += red[threadIdx.x + s];
        __syncthreads();
    }
    if (threadIdx.x == 0) g_sums[e] = red[0];
}

// ---------------------------------------------------------------------------
// k2b: means, variance = E||x||^2 - ||Ex||^2, factor = s / sqrt(var).
// ---------------------------------------------------------------------------
__global__ void stats_pass(const float* __restrict__ s_in) {
    __shared__ float red[1024];
    const int t = threadIdx.x;               // 1024 threads
    const int i = t >> 5, j = t & 31;
    const float invM = 1.0f / (float)M_TOT;

    float mean = g_sums[i * PSTRIDE + j] * invM;   // 0 for strictly-upper slots
    g_stats[i * 32 + j] = mean;
    float val = -mean * mean;
    if (t < 32) val += g_sums[t * PSTRIDE + 32] * invM;
    red[t] = val;
    __syncthreads();
#pragma unroll
    for (int s = 512; s > 0; s >>= 1) {
        if (t < s) red[t] += red[t + s];
        __syncthreads();
    }
    if (t == 0) {
        float var = red[0];
        g_stats[1024] = s_in[0] / sqrtf(var);
    }
}

// ---------------------------------------------------------------------------
// Pass 3 (unchanged from R16, measured): coalesced column-major load of L
// into smem, center + geodesic rescale, L_out L_out^T with float4 broadcast
// reads, direct symmetric coalesced store.
// ---------------------------------------------------------------------------
__global__ void __launch_bounds__(THREADS) out_pass(float* __restrict__ out) {
    __shared__ float4 sbuf[WPB * 288];       // tiles
    __shared__ float  smean_cm[32 * 33];     // mean, column-major: [j*33 + i]
    __shared__ float  smean_d[32];           // logd means
    __shared__ float  sfac;

    for (int e = threadIdx.x; e < 1024; e += THREADS) {
        int i = e >> 5, j = e & 31;
        float v = g_stats[e];
        smean_cm[j * 33 + i] = (i == j) ? 0.f : v;   // diag handled separately
        if (i == j) smean_d[i] = v;
    }
    if (threadIdx.x == 0) sfac = g_stats[1024];
    __syncthreads();
    const float factor = sfac;

    const int lane = threadIdx.x & 31;
    const int wl   = threadIdx.x >> 5;
    float4* tile = sbuf + wl * 288;
    float*  tf   = (float*)tile;
    const int gw = blockIdx.x * WPB + wl;

    for (int m = gw; m < M_TOT; m += NWARPS) {
        // coalesced load of column-major L -> column-major smem tile tf[col*TS + row]
        const float4* ls = (const float4*)(g_L + (size_t)m * 1024);
#pragma unroll
        for (int q = 0; q < 8; q++) {
            float4 v = ls[q * 32 + lane];    // col 4q+lane/8, rows 4(lane&7)..+3
            tile[(4 * q + (lane >> 3)) * TS4 + (lane & 7)] = v;
        }
        __syncwarp();

        // centered / rescaled own row b (lane i = row i). Upper entries are 0
        // automatically (L upper zeros, mean strict-upper zeros).
        float dL    = tf[lane * TS + lane];          // L[i][i]  (stride-37: conflict-free)
        float mdiag = smean_d[lane];                 // logd mean (stride-1)
        float edc   = __expf(factor * (__logf(dL) - mdiag));
        float b[32];
#pragma unroll
        for (int j = 0; j < 32; j++) {
            float aj = tf[j * TS + lane];            // L[i][j]      (stride-1: conflict-free)
            float mj = smean_cm[j * 33 + lane];      // mean[i][j]   (stride-1: conflict-free)
            float v  = factor * (aj - mj);
            b[j] = (j == lane) ? edc : v;
        }
        // write b back into own column-major slots (only lane i touches (j,i))
#pragma unroll
        for (int j = 0; j < 32; j++) tf[j * TS + lane] = b[j];
        __syncwarp();

        // X_out row i: o[j] = sum_k b_i[k] * b_j[k]; k outer, j chunks of 4
        // (broadcast LDS.128 of column k = {b_j[k]}_j). b[k]=0 for k>lane
        // truncates the row; tile zeros truncate j<k.
        float o[32];
#pragma unroll
        for (int j = 0; j < 32; j++) o[j] = 0.f;
#pragma unroll
        for (int k = 0; k < 32; k++) {
            float bk = b[k];
#pragma unroll
            for (int q = k / 4; q < 8; q++) {
                float4 c = tile[k * TS4 + q];        // b_{4q..4q+3}[k], broadcast
                if (4*q+0 >= k) o[4*q+0] += bk * c.x;
                if (4*q+1 >= k) o[4*q+1] += bk * c.y;
                if (4*q+2 >= k) o[4*q+2] += bk * c.z;
                if (4*q+3 >= k) o[4*q+3] += bk * c.w;
            }
        }
        __syncwarp();   // all tile reads done before next iteration's tile write

        // DIRECT symmetric store: out[m][j][lane] = X_out[j][lane] = X_out[lane][j]
        float* od = out + (size_t)m * 1024;
#pragma unroll
        for (int j = 0; j < 32; j++)
            od[j * 32 + lane] = o[j];
    }
}

extern "C" void kernel_launch(void* const* d_in, const int* in_sizes, int n_in,
                              void* d_out, int out_size) {
    const float* X = (const float*)d_in[0];
    const float* s = (const float*)d_in[1];
    float* out = (float*)d_out;

    chol_pass1<<<BLOCKS, THREADS>>>(X);
    reduce2a<<<PART_ENTRIES, BLOCKS>>>();
    stats_pass<<<1, 1024>>>(s);
    out_pass<<<BLOCKS, THREADS>>>(out);
}